// round 12
// baseline (speedup 1.0000x reference)
#include <cuda_runtime.h>
#include <cstdint>

#define NBATCH 8
#define NTOT   32768
#define KDIM   128
#define NCH    18
#define TILE_N 64
#define CHUNK_TILES 29          // 18*29*64 = 33408 >= 32768; last chunk has 19 tiles
#define JACOBI_ITERS 14
#define THREADS 384             // 8 MMA warps + 4 producer warps
#define ROWB   272              // bytes per fp16 row: 128 f16 (256B) + 16 pad

// ---------------- global scratch (fully rewritten every replay) ----------------
__device__ float g_scr[NCH][NBATCH][KDIM][KDIM];  // split-K partials (LL quadrant unwritten/unread)
__device__ float g_msr[NCH][NBATCH][KDIM];        // rhs partials
__device__ float g_sa[NBATCH][KDIM][KDIM];
__device__ float g_mred[NBATCH][KDIM];

// ---------------- helpers ----------------
__device__ __forceinline__ uint32_t smem_u32(const void* p) {
    uint32_t a;
    asm("{ .reg .u64 t; cvta.to.shared.u64 t, %1; cvt.u32.u64 %0, t; }"
        : "=r"(a) : "l"(p));
    return a;
}
__device__ __forceinline__ void ldsm4t(uint32_t* r, uint32_t addr) {
    asm volatile("ldmatrix.sync.aligned.m8n8.x4.trans.shared.b16 {%0,%1,%2,%3}, [%4];"
                 : "=r"(r[0]), "=r"(r[1]), "=r"(r[2]), "=r"(r[3]) : "r"(addr));
}
__device__ __forceinline__ void mma_f16(float* d, const uint32_t* a, const uint32_t* b) {
    asm volatile(
        "mma.sync.aligned.m16n8k16.row.col.f32.f16.f16.f32 "
        "{%0,%1,%2,%3}, {%4,%5,%6,%7}, {%8,%9}, {%0,%1,%2,%3};"
        : "+f"(d[0]), "+f"(d[1]), "+f"(d[2]), "+f"(d[3])
        : "r"(a[0]), "r"(a[1]), "r"(a[2]), "r"(a[3]), "r"(b[0]), "r"(b[1]));
}
__device__ __forceinline__ uint32_t pack_h2(float lo, float hi) {
    uint32_t d;
    asm("cvt.rn.f16x2.f32 %0, %1, %2;" : "=r"(d) : "f"(hi), "f"(lo));
    return d;
}
// named barriers: full[s] = 1+s, empty[s] = 3+s; count = 384 (128 arrive + 256 sync or vice versa)
#define BAR_SYNC(id)   asm volatile("bar.sync %0, 384;"   :: "r"(id) : "memory")
#define BAR_ARRIVE(id) asm volatile("bar.arrive %0, 384;" :: "r"(id) : "memory")

// ---------------- kernel 1: warp-specialized split-K gram ----------------
__global__ void __launch_bounds__(THREADS, 1)
gram_kernel(const float* __restrict__ data, const float* __restrict__ mask,
            const float* __restrict__ mult) {
    __shared__ char Hs[2][TILE_N * ROWB];   // 34816 B, double-buffered fp16 tile
    __shared__ float mred[KDIM];
    const uint32_t smb = smem_u32(Hs);
    const int tid = threadIdx.x;
    const int wid = tid >> 5;
    const int lane = tid & 31;
    const int chunk = blockIdx.x;
    const int b = blockIdx.y;
    const int n_start = chunk * (CHUNK_TILES * TILE_N);
    const int T = min(CHUNK_TILES, (NTOT - n_start) / TILE_N);

    if (tid < KDIM) mred[tid] = 0.f;
    __syncthreads();

    if (wid >= 8) {
        // ================= producer warps (8..11) =================
        const int p = tid - 256;             // 0..127
        const int kq = (p & 31) * 4;         // k-quad
        const int prow0 = (p >> 5) * 16;     // this warp's 16 rows
        const float* maskb = mask + (size_t)b * NTOT;
        const float* datab = data + (size_t)b * NTOT;
        float macc[4] = {0.f, 0.f, 0.f, 0.f};

        for (int t = 0; t < T; ++t) {
            const int s = t & 1;
            if (t >= 2) BAR_SYNC(3 + s);     // wait H[s] consumed
            const int rbase = n_start + t * TILE_N;
            char* hp = Hs[s];
            #pragma unroll
            for (int i = 0; i < 16; ++i) {
                const int n = prow0 + i;
                const float4 v = *(const float4*)(mult + (size_t)(rbase + n) * KDIM + kq);
                const float w = __ldg(maskb + rbase + n);
                const float d = __ldg(datab + rbase + n);
                const float x0 = v.x * w, x1 = v.y * w;
                const float x2 = v.z * w, x3 = v.w * w;
                const float c = w * d;
                macc[0] = fmaf(v.x, c, macc[0]);
                macc[1] = fmaf(v.y, c, macc[1]);
                macc[2] = fmaf(v.z, c, macc[2]);
                macc[3] = fmaf(v.w, c, macc[3]);
                *(uint2*)(hp + n * ROWB + kq * 2) =
                    make_uint2(pack_h2(x0, x1), pack_h2(x2, x3));
            }
            BAR_ARRIVE(1 + s);               // signal H[s] full
        }
        // rhs partials
        atomicAdd(&mred[kq],     macc[0]);
        atomicAdd(&mred[kq + 1], macc[1]);
        atomicAdd(&mred[kq + 2], macc[2]);
        atomicAdd(&mred[kq + 3], macc[3]);
        __syncthreads();
        if (p < KDIM) g_msr[chunk][b][p] = mred[p];
    } else {
        // ================= consumer (MMA) warps (0..7) =================
        // warp output-tile assignment (upper-triangle, SMSP-balanced):
        //  w0:(0,0)x64 w1:(0,64)x64 w2:(32,0)x64 w3:(32,64)x64
        //  w4:(64,96)x32 w5:(64,64)x32 w6:(96,96)x32 w7:(96,64)x32
        const int i0 = (wid >> 1) * 32;
        const int j0 = (wid < 4) ? (wid & 1) * 64 : 96 - (wid & 1) * 32;
        const int ngw = (wid < 4) ? 4 : 2;

        // ldmatrix lane addressing (validated rounds 3-11)
        const int grp = lane >> 3, r = lane & 7;
        const uint32_t a_off = (uint32_t)(((grp & 2) ? 8 : 0) + r) * ROWB + (uint32_t)((grp & 1) ? 8 : 0) * 2;
        const uint32_t b_off = (uint32_t)(((grp & 1) ? 8 : 0) + r) * ROWB + (uint32_t)((grp & 2) ? 8 : 0) * 2;

        float acc[2][4][2][4];
        #pragma unroll
        for (int mt = 0; mt < 2; ++mt)
            #pragma unroll
            for (int g = 0; g < 4; ++g)
                #pragma unroll
                for (int nt = 0; nt < 2; ++nt)
                    #pragma unroll
                    for (int q = 0; q < 4; ++q) acc[mt][g][nt][q] = 0.f;

        for (int t = 0; t < T; ++t) {
            const int s = t & 1;
            BAR_SYNC(1 + s);                 // wait H[s] full
            const uint32_t base = smb + (uint32_t)s * (TILE_N * ROWB);
            #pragma unroll
            for (int ks = 0; ks < 4; ++ks) {
                const uint32_t kofs = base + (uint32_t)ks * 16 * ROWB;
                uint32_t af[2][4];
                ldsm4t(af[0], kofs + a_off + (uint32_t)(i0) * 2);
                ldsm4t(af[1], kofs + a_off + (uint32_t)(i0 + 16) * 2);
                #pragma unroll
                for (int g = 0; g < 4; ++g) {
                    if (g < ngw) {
                        const int jblk = j0 + g * 16;
                        uint32_t bh[4];
                        if (jblk == i0) {            // diag block: B-frag = perm(A-frag)
                            bh[0] = af[0][0]; bh[1] = af[0][2];
                            bh[2] = af[0][1]; bh[3] = af[0][3];
                        } else if (jblk == i0 + 16) {
                            bh[0] = af[1][0]; bh[1] = af[1][2];
                            bh[2] = af[1][1]; bh[3] = af[1][3];
                        } else {
                            ldsm4t(bh, kofs + b_off + (uint32_t)jblk * 2);
                        }
                        mma_f16(acc[0][g][0], af[0], bh + 0);
                        mma_f16(acc[0][g][1], af[0], bh + 2);
                        mma_f16(acc[1][g][0], af[1], bh + 0);
                        mma_f16(acc[1][g][1], af[1], bh + 2);
                    }
                }
            }
            BAR_ARRIVE(3 + s);               // signal H[s] consumed
        }
        __syncthreads();

        // ---- epilogue: plain STG of computed tiles to scratch ----
        const int dg = lane >> 2, dt = (lane & 3) * 2;
        #pragma unroll
        for (int mt = 0; mt < 2; ++mt) {
            #pragma unroll
            for (int g = 0; g < 4; ++g) {
                if (g < ngw) {
                    #pragma unroll
                    for (int nt = 0; nt < 2; ++nt) {
                        const int i = i0 + mt * 16 + dg;
                        const int j = j0 + g * 16 + nt * 8 + dt;
                        *(float2*)&g_scr[chunk][b][i][j]     = make_float2(acc[mt][g][nt][0], acc[mt][g][nt][1]);
                        *(float2*)&g_scr[chunk][b][i + 8][j] = make_float2(acc[mt][g][nt][2], acc[mt][g][nt][3]);
                    }
                }
            }
        }
    }
}

// ---------------- kernel 2: reduce split-K partials + symmetrize + rhs ----------------
__global__ void reduce_kernel() {
    const int idx = blockIdx.x * 256 + threadIdx.x;
    const int PER4 = NBATCH * KDIM * KDIM / 4;    // 32768 float4 slots
    if (idx < PER4) {
        const int b = idx >> 12;
        const int rem = idx & 4095;
        const int i = rem >> 5;
        const int j = (rem & 31) * 4;
        if (i >= 64 && j < 64) return;            // filled by mirror
        float4 s = make_float4(0.f, 0.f, 0.f, 0.f);
        #pragma unroll
        for (int c = 0; c < NCH; ++c) {
            const float4 v = *(const float4*)&g_scr[c][b][i][j];
            s.x += v.x; s.y += v.y; s.z += v.z; s.w += v.w;
        }
        *(float4*)&g_sa[b][i][j] = s;
        if (i < 64 && j >= 64) {                  // mirror into skipped quadrant
            g_sa[b][j][i]     = s.x;
            g_sa[b][j + 1][i] = s.y;
            g_sa[b][j + 2][i] = s.z;
            g_sa[b][j + 3][i] = s.w;
        }
    } else if (idx < PER4 + NBATCH * KDIM) {
        const int r = idx - PER4;
        const float* p = (const float*)g_msr + r;
        float s = 0.f;
        #pragma unroll
        for (int c = 0; c < NCH; ++c) s += p[c * NBATCH * KDIM];
        ((float*)g_mred)[r] = s;
    }
}

// ---------------- kernel 3: Jacobi solve (G fully register-resident) ----------------
__global__ void __launch_bounds__(256)
solve_kernel(const float* __restrict__ sigma_sq, float* __restrict__ out) {
    __shared__ float xs[2][KDIM];
    __shared__ float mv[KDIM];
    const int b = blockIdx.x;
    const int tid = threadIdx.x;            // 256
    const int i = tid >> 1;
    const int half = tid & 1;
    const int c0 = half * 64;
    const float sig = sigma_sq[0];

    float G[64];
    #pragma unroll
    for (int j4 = 0; j4 < 64; j4 += 4) {
        const float4 v = *(const float4*)&g_sa[b][i][c0 + j4];
        G[j4] = v.x; G[j4 + 1] = v.y; G[j4 + 2] = v.z; G[j4 + 3] = v.w;
    }
    if (half == (i >> 6)) G[i & 63] += sig;
    if (tid < KDIM) mv[tid] = g_mred[b][tid];

    float dval = (half == (i >> 6)) ? G[i & 63] : 0.f;
    dval += __shfl_xor_sync(0xffffffffu, dval, 1);
    const float di = 1.f / dval;
    __syncthreads();
    if (half == 0) xs[0][i] = mv[i] * di;
    __syncthreads();

    for (int it = 0; it < JACOBI_ITERS; ++it) {
        const float* xr = xs[it & 1];
        float* xw = xs[(it & 1) ^ 1];
        float s = 0.f;
        #pragma unroll
        for (int j = 0; j < 64; ++j) s = fmaf(G[j], xr[c0 + j], s);
        s += __shfl_xor_sync(0xffffffffu, s, 1);
        if (half == 0) xw[i] = xr[i] + di * (mv[i] - s);
        __syncthreads();
    }
    if (half == 0) out[b * KDIM + i] = xs[0][i];   // even iter count -> buffer 0
}

// ---------------- launch ----------------
extern "C" void kernel_launch(void* const* d_in, const int* in_sizes, int n_in,
                              void* d_out, int out_size) {
    const float* data  = (const float*)d_in[0];
    const float* mask  = (const float*)d_in[1];
    const float* mult  = (const float*)d_in[2];
    const float* sigma = (const float*)d_in[3];
    float* out = (float*)d_out;

    dim3 grid(NCH, NBATCH);
    gram_kernel<<<grid, THREADS>>>(data, mask, mult);

    const int total4 = NBATCH * KDIM * KDIM / 4 + NBATCH * KDIM;
    reduce_kernel<<<(total4 + 255) / 256, 256>>>();

    solve_kernel<<<NBATCH, 256>>>(sigma, out);
}